// round 5
// baseline (speedup 1.0000x reference)
#include <cuda_runtime.h>

#define B_      32
#define NOTES_  78
#define T_      128
#define IN_     80
#define H_      128
#define NSEQ1   (B_ * NOTES_)          // 2496
#define SPB     17                      // sequences per block (148*17 = 2516 >= 2496)
#define NBLK    148
#define KK      104                     // float2 slices per gate row: 40 (x) + 64 (h)
#define KPAD    108                     // padded for unconditional prefetch

// ---------------- device scratch (no allocations allowed) ----------------
__device__ float2 g_wpk[KPAD * 512];                       // packed transposed weights [kk][row]
__device__ float  g_xpj[(size_t)NSEQ1 * T_ * 8];           // fused note-LSTM input projection

// ---------------- helpers ----------------
__device__ __forceinline__ float2 upk2(unsigned long long v) {
    float lo, hi;
    asm("mov.b64 {%0,%1}, %2;" : "=f"(lo), "=f"(hi) : "l"(v));
    float2 f; f.x = lo; f.y = hi; return f;
}
__device__ __forceinline__ void fma2(unsigned long long& a, unsigned long long w, unsigned long long d) {
    asm("fma.rn.f32x2 %0, %1, %2, %0;" : "+l"(a) : "l"(w), "l"(d));
}
__device__ __forceinline__ float sigf(float x)      { return __fdividef(1.f, 1.f + __expf(-x)); }
__device__ __forceinline__ float tanhfast(float x)  { return 2.f * sigf(2.f * x) - 1.f; }

// ---------------- weight packing: wT[kk][512] float2, k-major pairs ----------------
__global__ void pack_w_kernel(const float* __restrict__ Wih, const float* __restrict__ Whh) {
    int idx = blockIdx.x * blockDim.x + threadIdx.x;
    if (idx >= KPAD * 512) return;
    int kk = idx >> 9;
    int r  = idx & 511;
    float2 v = make_float2(0.f, 0.f);
    if (kk < 40) {                        // x-part: Wih_t[r][2kk], [2kk+1]
        v.x = Wih[r * IN_ + 2 * kk];
        v.y = Wih[r * IN_ + 2 * kk + 1];
    } else if (kk < KK) {                 // h-part: Whh_t[r][2j], [2j+1]
        int j = kk - 40;
        v.x = Whh[r * H_ + 2 * j];
        v.y = Whh[r * H_ + 2 * j + 1];
    }
    g_wpk[kk * 512 + r] = v;
}

// ---------------- stage 1: time LSTM (persistent, 1 block/SM) ----------------
// Thread tid owns gate rows (tid, tid+256):
//   tid in [0,128):   rows = (i-gate j=tid,      g-gate j=tid)
//   tid in [128,256): rows = (f-gate j=tid-128,  o-gate j=tid-128)
__global__ __launch_bounds__(256, 1) void stage1_kernel(
    const float* __restrict__ x,
    const float* __restrict__ bih, const float* __restrict__ bhh,
    const float* __restrict__ Wihn)
{
    __shared__ float2 sdata[SPB][KK];     // [s][0:40)=x_t pairs, [s][40:104)=h pairs
    __shared__ float2 sfo[128][SPB];      // (sig(f), sig(o)) exchange
    __shared__ float  sWn[8 * H_];        // Wih_n for fused projection

    const int tid  = threadIdx.x;
    const int seq0 = blockIdx.x * SPB;
    const int r0 = tid, r1 = tid + 256;
    const float bias0 = bih[r0] + bhh[r0];
    const float bias1 = bih[r1] + bhh[r1];
    const int j = tid & 127;

    for (int i = tid; i < 8 * H_; i += 256) sWn[i] = Wihn[i];

    float* df = &sdata[0][0].x;           // flat float view: df[s*208 + f]
    for (int i = tid; i < SPB * KK * 2; i += 256) df[i] = 0.f;

    float c[SPB];
    #pragma unroll
    for (int s = 0; s < SPB; s++) c[s] = 0.f;

    const unsigned long long* wp = reinterpret_cast<const unsigned long long*>(g_wpk);
    const unsigned long long* sd = reinterpret_cast<const unsigned long long*>(&sdata[0][0]);

    for (int t = 0; t < T_; t++) {
        // ---- stage x_t into SMEM (coalesced) ----
        for (int idx = tid; idx < SPB * IN_; idx += 256) {
            int s = idx / IN_;
            int i = idx - s * IN_;
            int seq = seq0 + s; if (seq >= NSEQ1) seq = NSEQ1 - 1;
            df[s * (KK * 2) + i] = x[((size_t)seq * T_ + t) * IN_ + i];
        }
        __syncthreads();                  // x ready; h(t-1) ready

        // ---- matvec: g[r] = W_cat[r] . [x_t ; h] for 17 seqs, f32x2 ----
        unsigned long long acc0[SPB], acc1[SPB];
        #pragma unroll
        for (int s = 0; s < SPB; s++) { acc0[s] = 0ull; acc1[s] = 0ull; }

        unsigned long long w0[4], w1[4];  // prefetch ring, depth 4
        #pragma unroll
        for (int p = 0; p < 4; p++) { w0[p] = wp[p * 512 + r0]; w1[p] = wp[p * 512 + r1]; }

        for (int i = 0; i < KK / 4; i++) {
            #pragma unroll
            for (int u = 0; u < 4; u++) {
                const int kk = i * 4 + u;
                const unsigned long long cw0 = w0[u], cw1 = w1[u];
                w0[u] = wp[(kk + 4) * 512 + r0];      // prefetch (padded region safe)
                w1[u] = wp[(kk + 4) * 512 + r1];
                #pragma unroll
                for (int s = 0; s < SPB; s++) {
                    unsigned long long d = sd[s * KK + kk];   // warp-broadcast
                    fma2(acc0[s], cw0, d);
                    fma2(acc1[s], cw1, d);
                }
            }
        }

        // ---- activations + partner exchange ----
        float ia[SPB], ga[SPB];
        if (tid >= 128) {                 // f & o rows
            #pragma unroll
            for (int s = 0; s < SPB; s++) {
                float2 a0 = upk2(acc0[s]); float gf = a0.x + a0.y + bias0;
                float2 a1 = upk2(acc1[s]); float go = a1.x + a1.y + bias1;
                sfo[j][s] = make_float2(sigf(gf), sigf(go));
            }
        } else {                          // i & g rows
            #pragma unroll
            for (int s = 0; s < SPB; s++) {
                float2 a0 = upk2(acc0[s]); float gi = a0.x + a0.y + bias0;
                float2 a1 = upk2(acc1[s]); float gg = a1.x + a1.y + bias1;
                ia[s] = sigf(gi);
                ga[s] = tanhfast(gg);
            }
        }
        __syncthreads();                  // sfo ready; matvec reads done

        // ---- cell update (threads 0..127 own cell j, all 17 seqs) ----
        if (tid < 128) {
            #pragma unroll
            for (int s = 0; s < SPB; s++) {
                float2 fo = sfo[j][s];
                c[s] = fo.x * c[s] + ia[s] * ga[s];
                float h = fo.y * tanhfast(c[s]);
                df[s * (KK * 2) + 80 + j] = h;        // h region
            }
        }
        __syncthreads();                  // h(t) ready

        // ---- fused note-LSTM input projection: xproj[seq][t][row] = Wih_n[row].h ----
        if (tid < SPB * 8) {
            int s = tid >> 3, row = tid & 7;
            const float2* hv = &sdata[s][40];
            const float2* wv = reinterpret_cast<const float2*>(&sWn[row * H_]);
            float acc = 0.f;
            #pragma unroll
            for (int jj = 0; jj < 64; jj++) {
                float2 h2 = hv[jj], w2 = wv[jj];
                acc = fmaf(h2.x, w2.x, fmaf(h2.y, w2.y, acc));
            }
            int seq = seq0 + s;
            if (seq < NSEQ1) g_xpj[((size_t)seq * T_ + t) * 8 + row] = acc;
        }
        // next iteration's x staging touches a disjoint SMEM region; its
        // __syncthreads orders everything before the next matvec.
    }
}

// ---------------- stage 2: note LSTM (hidden=2), one thread per (b,t) ----------------
__global__ __launch_bounds__(128) void stage2_kernel(
    const float* __restrict__ Whhn,
    const float* __restrict__ bihn, const float* __restrict__ bhhn,
    float* __restrict__ out)
{
    int g = blockIdx.x * 128 + threadIdx.x;    // 0..4095
    int b = g >> 7, t = g & 127;

    float W[16];
    #pragma unroll
    for (int i = 0; i < 16; i++) W[i] = Whhn[i];
    float bs[8];
    #pragma unroll
    for (int i = 0; i < 8; i++) bs[i] = bihn[i] + bhhn[i];

    float h0 = 0.f, h1 = 0.f, c0 = 0.f, c1 = 0.f;
    const float4* xp = reinterpret_cast<const float4*>(g_xpj);
    float* op = out + ((size_t)b * T_ + t) * (NOTES_ * 2);

    for (int note = 0; note < NOTES_; note++) {
        size_t base = ((size_t)(b * NOTES_ + note) * T_ + t) * 2;   // float4 index
        float4 xa = xp[base];       // rows 0..3 : i0 i1 f0 f1
        float4 xb = xp[base + 1];   // rows 4..7 : g0 g1 o0 o1
        float gi0 = xa.x + bs[0] + W[0]  * h0 + W[1]  * h1;
        float gi1 = xa.y + bs[1] + W[2]  * h0 + W[3]  * h1;
        float gf0 = xa.z + bs[2] + W[4]  * h0 + W[5]  * h1;
        float gf1 = xa.w + bs[3] + W[6]  * h0 + W[7]  * h1;
        float gg0 = xb.x + bs[4] + W[8]  * h0 + W[9]  * h1;
        float gg1 = xb.y + bs[5] + W[10] * h0 + W[11] * h1;
        float go0 = xb.z + bs[6] + W[12] * h0 + W[13] * h1;
        float go1 = xb.w + bs[7] + W[14] * h0 + W[15] * h1;
        c0 = sigf(gf0) * c0 + sigf(gi0) * tanhfast(gg0);
        c1 = sigf(gf1) * c1 + sigf(gi1) * tanhfast(gg1);
        h0 = sigf(go0) * tanhfast(c0);
        h1 = sigf(go1) * tanhfast(c1);
        op[note * 2]     = h0;
        op[note * 2 + 1] = h1;
    }
}

// ---------------- launch ----------------
extern "C" void kernel_launch(void* const* d_in, const int* in_sizes, int n_in,
                              void* d_out, int out_size)
{
    const float* x     = (const float*)d_in[0];
    const float* Wih_t = (const float*)d_in[1];
    const float* Whh_t = (const float*)d_in[2];
    const float* bih_t = (const float*)d_in[3];
    const float* bhh_t = (const float*)d_in[4];
    const float* Wih_n = (const float*)d_in[5];
    const float* Whh_n = (const float*)d_in[6];
    const float* bih_n = (const float*)d_in[7];
    const float* bhh_n = (const float*)d_in[8];
    float* out = (float*)d_out;

    pack_w_kernel<<<(KPAD * 512 + 255) / 256, 256>>>(Wih_t, Whh_t);
    stage1_kernel<<<NBLK, 256>>>(x, bih_t, bhh_t, Wih_n);
    stage2_kernel<<<(B_ * T_) / 128, 128>>>(Whh_n, bih_n, bhh_n, out);
}